// round 2
// baseline (speedup 1.0000x reference)
#include <cuda_runtime.h>
#include <math.h>

#define HH 512
#define WWPIX 512
#define WW 16                 // 32-bit words per row
#define NWORDS (HH * WW)      // 8192 words per image
#define NB 32                 // batch
#define SMEM_BYTES (2 * NWORDS * 4)

__device__ float g_partial[NB];

__device__ __forceinline__ unsigned ldw(const unsigned* buf, int r, int wc) {
    if ((unsigned)r >= (unsigned)HH || (unsigned)wc >= (unsigned)WW) return 0u;
    return buf[r * WW + wc];
}

__device__ __forceinline__ void csa(unsigned a, unsigned b, unsigned c,
                                    unsigned& s, unsigned& cy) {
    unsigned t = a ^ b;
    s = t ^ c;
    cy = (a & b) | (t & c);
}

// One Zhang-Suen substep on an 8-row x 1-word vertical strip. src -> dst.
// Returns nonzero if any pixel changed in this strip.
__device__ unsigned substep_strip(const unsigned* __restrict__ src,
                                  unsigned* __restrict__ dst,
                                  int r0, int wc, bool first) {
    unsigned diff = 0;
    unsigned ul = ldw(src, r0 - 1, wc - 1);
    unsigned uc = ldw(src, r0 - 1, wc);
    unsigned ur = ldw(src, r0 - 1, wc + 1);
    unsigned ml = ldw(src, r0, wc - 1);
    unsigned mc = ldw(src, r0, wc);
    unsigned mr = ldw(src, r0, wc + 1);
#pragma unroll
    for (int k = 0; k < 8; k++) {
        int r = r0 + k;
        unsigned dl = ldw(src, r + 1, wc - 1);
        unsigned dc = ldw(src, r + 1, wc);
        unsigned dr = ldw(src, r + 1, wc + 1);

        // neighbor bit-vectors (bit j = value of that neighbor of pixel j)
        unsigned Nv  = uc;
        unsigned Sv  = dc;
        unsigned Wv  = (mc << 1) | (ml >> 31);
        unsigned Ev  = (mc >> 1) | (mr << 31);
        unsigned NWv = (uc << 1) | (ul >> 31);
        unsigned NEv = (uc >> 1) | (ur << 31);
        unsigned SWv = (dc << 1) | (dl >> 31);
        unsigned SEv = (dc >> 1) | (dr << 31);

        // Bn = popcount of 8 neighbors, bitsliced into b0..b3 via CSA tree
        unsigned s1, c1, s2, c2, s3, c3;
        csa(Nv, NEv, Ev, s1, c1);
        csa(SEv, Sv, SWv, s2, c2);
        csa(Wv, NWv, s1, s3, c3);
        unsigned b0 = s2 ^ s3;
        unsigned cA = s2 & s3;
        unsigned s5, c5;
        csa(c1, c2, c3, s5, c5);
        unsigned b1 = s5 ^ cA;
        unsigned cB = s5 & cA;
        unsigned b2 = c5 ^ cB;
        unsigned b3 = c5 & cB;
        // 2 <= Bn <= 6  <=>  (Bn>=2) & !(Bn==7) & !(Bn==8)
        unsigned condB = (b1 | b2) & ~b3 & ~(b0 & b1 & b2);

        // A == 1: exactly one 0->1 transition in cyclic seq P2..P9,P2
        // seq: N, NE, E, SE, S, SW, W, NW, N
        unsigned t0 = ~Nv & NEv;
        unsigned t1 = ~NEv & Ev;
        unsigned t2 = ~Ev & SEv;
        unsigned t3 = ~SEv & Sv;
        unsigned t4 = ~Sv & SWv;
        unsigned t5 = ~SWv & Wv;
        unsigned t6 = ~Wv & NWv;
        unsigned t7 = ~NWv & Nv;
        unsigned acc = t0, ge2 = 0;
        ge2 |= acc & t1; acc |= t1;
        ge2 |= acc & t2; acc |= t2;
        ge2 |= acc & t3; acc |= t3;
        ge2 |= acc & t4; acc |= t4;
        ge2 |= acc & t5; acc |= t5;
        ge2 |= acc & t6; acc |= t6;
        ge2 |= acc & t7; acc |= t7;
        unsigned A1 = acc & ~ge2;

        // c1 & c2 combined: first:  ~(E&S&(N|W)) ; second: ~(N&W&(E|S))
        unsigned kill = first ? (Ev & Sv & (Nv | Wv))
                              : (Nv & Wv & (Ev | Sv));

        unsigned remove = mc & condB & A1 & ~kill;
        unsigned neww = mc & ~remove;
        dst[r * WW + wc] = neww;
        diff |= neww ^ mc;

        ul = ml; uc = mc; ur = mr;
        ml = dl; mc = dc; mr = dr;
    }
    return diff;
}

__global__ void __launch_bounds__(1024, 1)
skel_loss_kernel(const float* __restrict__ logits,
                 const float* __restrict__ gt) {
    extern __shared__ unsigned smem[];
    unsigned* bufA = smem;           // current image bitmap
    unsigned* bufB = smem + NWORDS;  // scratch / tubed
    __shared__ int s_changed;
    __shared__ float s_redI[32];
    __shared__ float s_redS[32];

    const int tid = threadIdx.x;
    const int b = blockIdx.x;
    const size_t base = (size_t)b * HH * WWPIX;
    const float* m = gt + base;
    const float* lg = logits + base;

    // ---- load mask bits into bufA via warp ballot ----
    for (int idx = tid; idx < HH * WWPIX; idx += 1024) {
        unsigned bit = (m[idx] > 0.0f) ? 1u : 0u;
        unsigned word = __ballot_sync(0xffffffffu, bit);
        if ((tid & 31) == 0) bufA[idx >> 5] = word;
    }
    if (tid == 0) s_changed = 0;
    __syncthreads();

    const int wc = tid & 15;
    const int r0 = (tid >> 4) * 8;

    // ---- iterative thinning to fixed point ----
    for (int it = 0; it < 256; it++) {
        unsigned d1 = substep_strip(bufA, bufB, r0, wc, true);
        __syncthreads();
        unsigned d2 = substep_strip(bufB, bufA, r0, wc, false);
        if (d1 | d2) s_changed = 1;
        __syncthreads();
        if (!s_changed) break;
        if (tid == 0) s_changed = 0;
        __syncthreads();
    }
    __syncthreads();

    // ---- dilate with disk radius 2 (dy^2+dx^2 <= 4), bufA -> bufB ----
#pragma unroll
    for (int k = 0; k < 8; k++) {
        int r = r0 + k;
        unsigned a_l = ldw(bufA, r, wc - 1);
        unsigned a_c = ldw(bufA, r, wc);
        unsigned a_r = ldw(bufA, r, wc + 1);
        unsigned u_l = ldw(bufA, r - 1, wc - 1);
        unsigned u_c = ldw(bufA, r - 1, wc);
        unsigned u_r = ldw(bufA, r - 1, wc + 1);
        unsigned d_l = ldw(bufA, r + 1, wc - 1);
        unsigned d_c = ldw(bufA, r + 1, wc);
        unsigned d_r = ldw(bufA, r + 1, wc + 1);
        unsigned uu = ldw(bufA, r - 2, wc);
        unsigned dd = ldw(bufA, r + 2, wc);

        unsigned mid = a_c
            | ((a_c << 1) | (a_l >> 31)) | ((a_c >> 1) | (a_r << 31))
            | ((a_c << 2) | (a_l >> 30)) | ((a_c >> 2) | (a_r << 30));
        unsigned up1 = u_c
            | ((u_c << 1) | (u_l >> 31)) | ((u_c >> 1) | (u_r << 31));
        unsigned dn1 = d_c
            | ((d_c << 1) | (d_l >> 31)) | ((d_c >> 1) | (d_r << 31));
        bufB[r * WW + wc] = mid | up1 | dn1 | uu | dd;
    }
    __syncthreads();

    // ---- masked reduction: I = sum sigmoid(logit)*final, S = sum final ----
    // final = tubed_bit * m (m is the original float mask value)
    float iacc = 0.0f, sacc = 0.0f;
#pragma unroll
    for (int k = 0; k < 8; k++) {
        int r = r0 + k;
        unsigned t = bufB[r * WW + wc];
        if (t) {
            int pbase = r * WWPIX + wc * 32;
            const float4* m4 = (const float4*)(m + pbase);
            const float4* l4 = (const float4*)(lg + pbase);
#pragma unroll
            for (int q = 0; q < 8; q++) {
                unsigned nib = (t >> (q * 4)) & 0xF;
                if (nib) {
                    float4 mv = m4[q];
                    float4 lv = l4[q];
                    if (nib & 1u) {
                        sacc += mv.x;
                        iacc += mv.x * __fdividef(1.0f, 1.0f + __expf(-lv.x));
                    }
                    if (nib & 2u) {
                        sacc += mv.y;
                        iacc += mv.y * __fdividef(1.0f, 1.0f + __expf(-lv.y));
                    }
                    if (nib & 4u) {
                        sacc += mv.z;
                        iacc += mv.z * __fdividef(1.0f, 1.0f + __expf(-lv.z));
                    }
                    if (nib & 8u) {
                        sacc += mv.w;
                        iacc += mv.w * __fdividef(1.0f, 1.0f + __expf(-lv.w));
                    }
                }
            }
        }
    }

    // block reduction
#pragma unroll
    for (int off = 16; off > 0; off >>= 1) {
        iacc += __shfl_down_sync(0xffffffffu, iacc, off);
        sacc += __shfl_down_sync(0xffffffffu, sacc, off);
    }
    if ((tid & 31) == 0) {
        s_redI[tid >> 5] = iacc;
        s_redS[tid >> 5] = sacc;
    }
    __syncthreads();
    if (tid < 32) {
        float vi = s_redI[tid];
        float vs = s_redS[tid];
#pragma unroll
        for (int off = 16; off > 0; off >>= 1) {
            vi += __shfl_down_sync(0xffffffffu, vi, off);
            vs += __shfl_down_sync(0xffffffffu, vs, off);
        }
        if (tid == 0) {
            g_partial[b] = 1.0f - (vi + 1e-6f) / (vs + 1e-6f);
        }
    }
}

__global__ void finalize_kernel(float* __restrict__ out) {
    float v = g_partial[threadIdx.x];
#pragma unroll
    for (int off = 16; off > 0; off >>= 1) {
        v += __shfl_down_sync(0xffffffffu, v, off);
    }
    if (threadIdx.x == 0) out[0] = v * (1.0f / (float)NB);
}

extern "C" void kernel_launch(void* const* d_in, const int* in_sizes, int n_in,
                              void* d_out, int out_size) {
    const float* logits = (const float*)d_in[0];
    const float* gt = (const float*)d_in[1];
    float* out = (float*)d_out;

    cudaFuncSetAttribute(skel_loss_kernel,
                         cudaFuncAttributeMaxDynamicSharedMemorySize, SMEM_BYTES);
    skel_loss_kernel<<<NB, 1024, SMEM_BYTES>>>(logits, gt);
    finalize_kernel<<<1, 32>>>(out);
}

// round 3
// speedup vs baseline: 1.0009x; 1.0009x over previous
#include <cuda_runtime.h>
#include <math.h>

#define HH 512
#define WWPIX 512
#define WW 16                 // 32-bit words per row
#define NWORDS (HH * WW)      // 8192 words per image
#define NB 32                 // batch
#define SMEM_BYTES (2 * NWORDS * 4)

__device__ float g_partial[NB];

__device__ __forceinline__ unsigned ldw(const unsigned* buf, int r, int wc) {
    if ((unsigned)r >= (unsigned)HH || (unsigned)wc >= (unsigned)WW) return 0u;
    return buf[r * WW + wc];
}

__device__ __forceinline__ void csa(unsigned a, unsigned b, unsigned c,
                                    unsigned& s, unsigned& cy) {
    unsigned t = a ^ b;
    s = t ^ c;
    cy = (a & b) | (t & c);
}

// One Zhang-Suen substep on an 8-row x 1-word vertical strip. src -> dst.
// Returns nonzero if any pixel changed in this strip.
__device__ unsigned substep_strip(const unsigned* __restrict__ src,
                                  unsigned* __restrict__ dst,
                                  int r0, int wc, bool first) {
    unsigned diff = 0;
    unsigned ul = ldw(src, r0 - 1, wc - 1);
    unsigned uc = ldw(src, r0 - 1, wc);
    unsigned ur = ldw(src, r0 - 1, wc + 1);
    unsigned ml = ldw(src, r0, wc - 1);
    unsigned mc = ldw(src, r0, wc);
    unsigned mr = ldw(src, r0, wc + 1);
#pragma unroll
    for (int k = 0; k < 8; k++) {
        int r = r0 + k;
        unsigned dl = ldw(src, r + 1, wc - 1);
        unsigned dc = ldw(src, r + 1, wc);
        unsigned dr = ldw(src, r + 1, wc + 1);

        // neighbor bit-vectors (bit j = value of that neighbor of pixel j)
        unsigned Nv  = uc;
        unsigned Sv  = dc;
        unsigned Wv  = (mc << 1) | (ml >> 31);
        unsigned Ev  = (mc >> 1) | (mr << 31);
        unsigned NWv = (uc << 1) | (ul >> 31);
        unsigned NEv = (uc >> 1) | (ur << 31);
        unsigned SWv = (dc << 1) | (dl >> 31);
        unsigned SEv = (dc >> 1) | (dr << 31);

        // Bn = popcount of 8 neighbors, bitsliced into b0..b3 via CSA tree
        unsigned s1, c1, s2, c2, s3, c3;
        csa(Nv, NEv, Ev, s1, c1);
        csa(SEv, Sv, SWv, s2, c2);
        csa(Wv, NWv, s1, s3, c3);
        unsigned b0 = s2 ^ s3;
        unsigned cA = s2 & s3;
        unsigned s5, c5;
        csa(c1, c2, c3, s5, c5);
        unsigned b1 = s5 ^ cA;
        unsigned cB = s5 & cA;
        unsigned b2 = c5 ^ cB;
        unsigned b3 = c5 & cB;
        // 2 <= Bn <= 6  <=>  (Bn>=2) & !(Bn==7) & !(Bn==8)
        unsigned condB = (b1 | b2) & ~b3 & ~(b0 & b1 & b2);

        // A == 1: exactly one 0->1 transition in cyclic seq P2..P9,P2
        // seq: N, NE, E, SE, S, SW, W, NW, N
        unsigned t0 = ~Nv & NEv;
        unsigned t1 = ~NEv & Ev;
        unsigned t2 = ~Ev & SEv;
        unsigned t3 = ~SEv & Sv;
        unsigned t4 = ~Sv & SWv;
        unsigned t5 = ~SWv & Wv;
        unsigned t6 = ~Wv & NWv;
        unsigned t7 = ~NWv & Nv;
        unsigned acc = t0, ge2 = 0;
        ge2 |= acc & t1; acc |= t1;
        ge2 |= acc & t2; acc |= t2;
        ge2 |= acc & t3; acc |= t3;
        ge2 |= acc & t4; acc |= t4;
        ge2 |= acc & t5; acc |= t5;
        ge2 |= acc & t6; acc |= t6;
        ge2 |= acc & t7; acc |= t7;
        unsigned A1 = acc & ~ge2;

        // c1 & c2 combined: first:  ~(E&S&(N|W)) ; second: ~(N&W&(E|S))
        unsigned kill = first ? (Ev & Sv & (Nv | Wv))
                              : (Nv & Wv & (Ev | Sv));

        unsigned remove = mc & condB & A1 & ~kill;
        unsigned neww = mc & ~remove;
        dst[r * WW + wc] = neww;
        diff |= neww ^ mc;

        ul = ml; uc = mc; ur = mr;
        ml = dl; mc = dc; mr = dr;
    }
    return diff;
}

__global__ void __launch_bounds__(1024, 1)
skel_loss_kernel(const float* __restrict__ logits,
                 const float* __restrict__ gt) {
    extern __shared__ unsigned smem[];
    unsigned* bufA = smem;           // current image bitmap
    unsigned* bufB = smem + NWORDS;  // scratch / tubed
    __shared__ int s_changed;
    __shared__ float s_redI[32];
    __shared__ float s_redS[32];

    const int tid = threadIdx.x;
    const int b = blockIdx.x;
    const size_t base = (size_t)b * HH * WWPIX;
    const float* m = gt + base;
    const float* lg = logits + base;

    // ---- load mask bits into bufA via warp ballot ----
    for (int idx = tid; idx < HH * WWPIX; idx += 1024) {
        unsigned bit = (m[idx] > 0.0f) ? 1u : 0u;
        unsigned word = __ballot_sync(0xffffffffu, bit);
        if ((tid & 31) == 0) bufA[idx >> 5] = word;
    }
    if (tid == 0) s_changed = 0;
    __syncthreads();

    const int wc = tid & 15;
    const int r0 = (tid >> 4) * 8;

    // ---- iterative thinning to fixed point ----
    for (int it = 0; it < 256; it++) {
        unsigned d1 = substep_strip(bufA, bufB, r0, wc, true);
        __syncthreads();
        unsigned d2 = substep_strip(bufB, bufA, r0, wc, false);
        if (d1 | d2) s_changed = 1;
        __syncthreads();
        if (!s_changed) break;
        if (tid == 0) s_changed = 0;
        __syncthreads();
    }
    __syncthreads();

    // ---- dilate with disk radius 2 (dy^2+dx^2 <= 4), bufA -> bufB ----
#pragma unroll
    for (int k = 0; k < 8; k++) {
        int r = r0 + k;
        unsigned a_l = ldw(bufA, r, wc - 1);
        unsigned a_c = ldw(bufA, r, wc);
        unsigned a_r = ldw(bufA, r, wc + 1);
        unsigned u_l = ldw(bufA, r - 1, wc - 1);
        unsigned u_c = ldw(bufA, r - 1, wc);
        unsigned u_r = ldw(bufA, r - 1, wc + 1);
        unsigned d_l = ldw(bufA, r + 1, wc - 1);
        unsigned d_c = ldw(bufA, r + 1, wc);
        unsigned d_r = ldw(bufA, r + 1, wc + 1);
        unsigned uu = ldw(bufA, r - 2, wc);
        unsigned dd = ldw(bufA, r + 2, wc);

        unsigned mid = a_c
            | ((a_c << 1) | (a_l >> 31)) | ((a_c >> 1) | (a_r << 31))
            | ((a_c << 2) | (a_l >> 30)) | ((a_c >> 2) | (a_r << 30));
        unsigned up1 = u_c
            | ((u_c << 1) | (u_l >> 31)) | ((u_c >> 1) | (u_r << 31));
        unsigned dn1 = d_c
            | ((d_c << 1) | (d_l >> 31)) | ((d_c >> 1) | (d_r << 31));
        bufB[r * WW + wc] = mid | up1 | dn1 | uu | dd;
    }
    __syncthreads();

    // ---- masked reduction: I = sum sigmoid(logit)*final, S = sum final ----
    // final = tubed_bit * m (m is the original float mask value)
    float iacc = 0.0f, sacc = 0.0f;
#pragma unroll
    for (int k = 0; k < 8; k++) {
        int r = r0 + k;
        unsigned t = bufB[r * WW + wc];
        if (t) {
            int pbase = r * WWPIX + wc * 32;
            const float4* m4 = (const float4*)(m + pbase);
            const float4* l4 = (const float4*)(lg + pbase);
#pragma unroll
            for (int q = 0; q < 8; q++) {
                unsigned nib = (t >> (q * 4)) & 0xF;
                if (nib) {
                    float4 mv = m4[q];
                    float4 lv = l4[q];
                    if (nib & 1u) {
                        sacc += mv.x;
                        iacc += mv.x * __fdividef(1.0f, 1.0f + __expf(-lv.x));
                    }
                    if (nib & 2u) {
                        sacc += mv.y;
                        iacc += mv.y * __fdividef(1.0f, 1.0f + __expf(-lv.y));
                    }
                    if (nib & 4u) {
                        sacc += mv.z;
                        iacc += mv.z * __fdividef(1.0f, 1.0f + __expf(-lv.z));
                    }
                    if (nib & 8u) {
                        sacc += mv.w;
                        iacc += mv.w * __fdividef(1.0f, 1.0f + __expf(-lv.w));
                    }
                }
            }
        }
    }

    // block reduction
#pragma unroll
    for (int off = 16; off > 0; off >>= 1) {
        iacc += __shfl_down_sync(0xffffffffu, iacc, off);
        sacc += __shfl_down_sync(0xffffffffu, sacc, off);
    }
    if ((tid & 31) == 0) {
        s_redI[tid >> 5] = iacc;
        s_redS[tid >> 5] = sacc;
    }
    __syncthreads();
    if (tid < 32) {
        float vi = s_redI[tid];
        float vs = s_redS[tid];
#pragma unroll
        for (int off = 16; off > 0; off >>= 1) {
            vi += __shfl_down_sync(0xffffffffu, vi, off);
            vs += __shfl_down_sync(0xffffffffu, vs, off);
        }
        if (tid == 0) {
            g_partial[b] = 1.0f - (vi + 1e-6f) / (vs + 1e-6f);
        }
    }
}

__global__ void finalize_kernel(float* __restrict__ out) {
    float v = g_partial[threadIdx.x];
#pragma unroll
    for (int off = 16; off > 0; off >>= 1) {
        v += __shfl_down_sync(0xffffffffu, v, off);
    }
    if (threadIdx.x == 0) out[0] = v * (1.0f / (float)NB);
}

extern "C" void kernel_launch(void* const* d_in, const int* in_sizes, int n_in,
                              void* d_out, int out_size) {
    const float* logits = (const float*)d_in[0];
    const float* gt = (const float*)d_in[1];
    float* out = (float*)d_out;

    cudaFuncSetAttribute(skel_loss_kernel,
                         cudaFuncAttributeMaxDynamicSharedMemorySize, SMEM_BYTES);
    skel_loss_kernel<<<NB, 1024, SMEM_BYTES>>>(logits, gt);
    finalize_kernel<<<1, 32>>>(out);
}